// round 14
// baseline (speedup 1.0000x reference)
#include <cuda_runtime.h>
#include <cuda.h>
#include <cuda_bf16.h>
#include <cstdint>

#define EPSF 1e-5f
#define SBLK 592

// ---------------- device scratch ----------------
__device__ float g_part[SBLK * 384];   // [blk][stat(3)][chan(128)]
__device__ float g_mean[128];
__device__ float g_sig[128];

// ---------------- helpers ----------------
__device__ __forceinline__ float4 f4add(float4 a, float4 b) {
    return make_float4(a.x+b.x, a.y+b.y, a.z+b.z, a.w+b.w);
}
__device__ __forceinline__ float4 f4sub(float4 a, float4 b) {
    return make_float4(a.x-b.x, a.y-b.y, a.z-b.z, a.w-b.w);
}
__device__ __forceinline__ float4 f4abs(float4 a) {
    return make_float4(fabsf(a.x), fabsf(a.y), fabsf(a.z), fabsf(a.w));
}
__device__ __forceinline__ float4 f4zero() { return make_float4(0.f,0.f,0.f,0.f); }
__device__ __forceinline__ float cntf(int g) {
    int lo = g - 2 < 0 ? 0 : g - 2;
    int hi = g + 3 > 127 ? 127 : g + 3;
    return (float)(hi - lo + 1);
}
__device__ __forceinline__ uint32_t s2u(const void* p) {
    uint32_t a;
    asm("{ .reg .u64 t; cvta.to.shared.u64 t, %1; cvt.u32.u64 %0, t; }" : "=r"(a) : "l"(p));
    return a;
}

#define MBAR_INIT(mb, cnt) \
    asm volatile("mbarrier.init.shared.b64 [%0], %1;" :: "r"(mb), "r"(cnt) : "memory")
#define MBAR_EXPECT_TX(mb, bytes) \
    asm volatile("mbarrier.arrive.expect_tx.shared.b64 _, [%0], %1;" :: "r"(mb), "r"(bytes) : "memory")
#define MBAR_WAIT(mb, ph) do { \
    uint32_t _done = 0; \
    asm volatile("{\n\t.reg .pred p;\n\tmbarrier.try_wait.parity.acquire.cta.shared::cta.b64 p, [%1], %2;\n\tselp.b32 %0, 1, 0, p;\n\t}" \
        : "=r"(_done) : "r"(mb), "r"(ph) : "memory"); \
    if (!_done) { \
        asm volatile("{\n\t.reg .pred P1;\n\tWL%=:\n\tmbarrier.try_wait.parity.acquire.cta.shared::cta.b64 P1, [%0], %1, 0x989680;\n\t@P1 bra.uni WD%=;\n\tbra.uni WL%=;\n\tWD%=:\n\t}" \
            :: "r"(mb), "r"(ph) : "memory"); \
    } } while (0)

// ---------------- kernel 1: per-block partial stats ----------------
__global__ __launch_bounds__(256, 4)
void k_stats(const float4* __restrict__ x4, int n4)
{
    __shared__ float sbuf[8][32][12];
    const int tx = threadIdx.x;
    const int wz = tx >> 5, gg = tx & 31;

    float s0=0,s1=0,s2=0,s3=0, a0=0,a1=0,a2=0,a3=0, q0=0,q1=0,q2=0,q3=0;
    const int stride = SBLK * 256;
    #pragma unroll 4
    for (int i = blockIdx.x * 256 + tx; i < n4; i += stride) {
        float4 v = x4[i];
        s0 += v.x; a0 += fabsf(v.x); q0 += (v.x > 0.f ? 1.f : -1.f);
        s1 += v.y; a1 += fabsf(v.y); q1 += (v.y > 0.f ? 1.f : -1.f);
        s2 += v.z; a2 += fabsf(v.z); q2 += (v.z > 0.f ? 1.f : -1.f);
        s3 += v.w; a3 += fabsf(v.w); q3 += (v.w > 0.f ? 1.f : -1.f);
    }
    sbuf[wz][gg][0]=s0; sbuf[wz][gg][1]=s1; sbuf[wz][gg][2]=s2;  sbuf[wz][gg][3]=s3;
    sbuf[wz][gg][4]=a0; sbuf[wz][gg][5]=a1; sbuf[wz][gg][6]=a2;  sbuf[wz][gg][7]=a3;
    sbuf[wz][gg][8]=q0; sbuf[wz][gg][9]=q1; sbuf[wz][gg][10]=q2; sbuf[wz][gg][11]=q3;
    __syncthreads();
    for (int o = tx; o < 384; o += 256) {
        int stat = o >> 7, c = o & 127;
        int g2 = c >> 2, j2 = c & 3;
        float t = 0.f;
        #pragma unroll
        for (int z = 0; z < 8; ++z) t += sbuf[z][g2][stat*4 + j2];
        g_part[blockIdx.x * 384 + o] = t;
    }
}

// ---------------- kernel 2: fold partials ----------------
__global__ void k_reduce()
{
    const int c = blockIdx.x;
    const int t = threadIdx.x;
    float s0=0.f, s1=0.f, s2=0.f;
    for (int blk = t; blk < SBLK; blk += 128) {
        const float* p = g_part + blk * 384;
        s0 += p[c]; s1 += p[128 + c]; s2 += p[256 + c];
    }
    __shared__ float r0[128], r1[128], r2[128];
    r0[t]=s0; r1[t]=s1; r2[t]=s2;
    __syncthreads();
    #pragma unroll
    for (int off = 64; off > 0; off >>= 1) {
        if (t < off) { r0[t]+=r0[t+off]; r1[t]+=r1[t+off]; r2[t]+=r2[t+off]; }
        __syncthreads();
    }
    if (t == 0) {
        const float invN = 1.f / (32.f * 128.f * 128.f);
        float m = r0[0] * invN;
        g_mean[c] = m;
        g_sig[c]  = (r1[0] - m * r2[0]) * invN;
    }
}

// ---------------- kernel 3: fused local mean/MAD/blend ----------------
// grid (32 quads, 16 tiles, 32 batch), 256 threads, 3 CTAs/SM.
// smem (bytes):
//   sx @ 0     : [42][42] float4 = 28224  (TMA load target)
//   hx @ 28288 : [42][37] float4 = 24864  (reused as hd[37][37] in stage C)
//   df @ 53248 : [37][37] float4 = 21904
// Stage D writes results directly to GMEM (STG.128); no staging buffer.
#define N_SX (42*42)
#define OFF_SX 0
#define OFF_HX 28288
#define OFF_DF 53248
#define SMEMB (OFF_DF + 37*37*16)

__global__ __launch_bounds__(256, 3)
void k_main(const __grid_constant__ CUtensorMap tmin,
            const float* __restrict__ x,
            const float* __restrict__ gamma,
            const float* __restrict__ beta,
            const float* __restrict__ lbin,
            float4* __restrict__ out4,
            int use_tma)
{
    extern __shared__ __align__(128) char smdyn[];
    float4* sx = (float4*)(smdyn + OFF_SX);   // [42][42]
    float4* hx = (float4*)(smdyn + OFF_HX);   // [42][37]
    float4* df = (float4*)(smdyn + OFF_DF);   // [37][37]

    __shared__ __align__(8) uint64_t mbar;
    __shared__ float invW[37], invH[37];

    const int tx = threadIdx.x;
    const int quad = blockIdx.x;
    const int ox = (blockIdx.y & 3) * 32;
    const int oy = (blockIdx.y >> 2) * 32;
    const int b  = blockIdx.z;

    const uint32_t mb = s2u(&mbar);

    if (tx == 0) MBAR_INIT(mb, 1);
    __syncthreads();

    if (use_tma) {
        if (tx == 0) {
            MBAR_EXPECT_TX(mb, (uint32_t)(N_SX * 16));
            asm volatile(
                "cp.async.bulk.tensor.4d.shared::cta.global.tile.mbarrier::complete_tx::bytes "
                "[%0], [%1, {%2, %3, %4, %5}], [%6];"
                :: "r"(s2u(sx)), "l"(&tmin),
                   "r"(quad * 4), "r"(ox - 4), "r"(oy - 4), "r"(b),
                   "r"(mb) : "memory");
        }
    } else {
        const float4* xb = (const float4*)x;
        for (int p = tx; p < N_SX; p += 256) {
            int iy = p / 42, ix = p - iy * 42;
            int gr = oy - 4 + iy, gc = ox - 4 + ix;
            float4 v = f4zero();
            if ((unsigned)gr < 128u && (unsigned)gc < 128u)
                v = xb[((size_t)b * 16384 + gr * 128 + gc) * 32 + quad];
            sx[p] = v;
        }
    }

    // inverse window counts (overlaps the load)
    if (tx >= 160 && tx < 234) {
        int k = tx - 160;
        if (k < 37) invW[k] = 1.f / cntf(ox - 2 + k);
        else        invH[k - 37] = 1.f / cntf(oy - 2 + (k - 37));
    }

    if (use_tma) { MBAR_WAIT(mb, 0); }
    else __syncthreads();

    // Stage A: horizontal 6-box of x. 252 threads: (row y, chunk of 7 outputs).
    // 12 contiguous register-cached reads/thread; lane addr step 112B -> conflict-free.
    if (tx < 252) {
        int y = tx / 6;
        int j0 = (tx % 6) * 7;
        const float4* row = sx + y * 42;
        float4 v[12];
        #pragma unroll
        for (int k = 0; k < 12; ++k)
            v[k] = (j0 + k <= 41) ? row[j0 + k] : f4zero();
        float4* hrow = hx + y * 37;
        float4 s = f4add(f4add(f4add(v[0], v[1]), f4add(v[2], v[3])), v[4]);
        #pragma unroll
        for (int k = 0; k < 7; ++k) {
            s = f4add(s, v[k + 5]);
            if (j0 + k <= 36) hrow[j0 + k] = s;
            s = f4sub(s, v[k]);
        }
    }
    __syncthreads();

    // Stage B: vertical 6-box -> local mean; df = x - lm (0 outside image).
    // 148 threads: (col j, 4 segments of 10/9 rows). Lane-contiguous -> conflict-free.
    if (tx < 148) {
        int j = tx % 37, seg = tx / 37;
        int r0 = (seg == 0) ? 0 : (9 * seg + 1);
        int rn = (seg == 0) ? 10 : 9;
        float iw = invW[j];
        int gc = ox - 2 + j;
        bool cin = ((unsigned)gc < 128u);
        const float4* hcol = hx + j;
        float4 s = f4add(f4add(f4add(hcol[(r0+0)*37], hcol[(r0+1)*37]),
                               f4add(hcol[(r0+2)*37], hcol[(r0+3)*37])), hcol[(r0+4)*37]);
        #pragma unroll 5
        for (int it = 0; it < rn; ++it) {
            int r = r0 + it;
            s = f4add(s, hcol[(r + 5) * 37]);
            int gr = oy - 2 + r;
            float ic = iw * invH[r];
            float4 xv = sx[(r + 2) * 42 + (j + 2)];
            float4 dv = f4zero();
            if (cin && (unsigned)gr < 128u) {
                dv.x = xv.x - s.x * ic;
                dv.y = xv.y - s.y * ic;
                dv.z = xv.z - s.z * ic;
                dv.w = xv.w - s.w * ic;
            }
            df[r * 37 + j] = dv;
            s = f4sub(s, hcol[r * 37]);
        }
    }
    __syncthreads();

    // Stage C: horizontal 6-box of |df| -> hd (reuses hx). 185 threads:
    // (row r = tx%37 lane-fast -> bank step 20, distinct; chunk of 7 outputs).
    if (tx < 185) {
        int r = tx % 37;
        int u0 = (tx / 37) * 7;
        const float4* drow = df + r * 37;
        float4 v[12];
        #pragma unroll
        for (int k = 0; k < 12; ++k)
            v[k] = (u0 + k <= 36) ? f4abs(drow[u0 + k]) : f4zero();
        float4* hrow = hx + r * 37;
        float4 s = f4add(f4add(f4add(v[0], v[1]), f4add(v[2], v[3])), v[4]);
        #pragma unroll
        for (int k = 0; k < 7; ++k) {
            s = f4add(s, v[k + 5]);
            if (u0 + k <= 31) hrow[u0 + k] = s;
            s = f4sub(s, v[k]);
        }
    }
    __syncthreads();

    // Stage D: vertical 6-box of hd -> mad; blend + affine; direct STG.128 to GMEM.
    // 128 threads: (col u, 4 segments of 8 rows). Lane-contiguous smem -> conflict-free.
    if (tx < 128) {
        int u = tx & 31, seg = tx >> 5;
        int v0 = seg * 8;
        float iw = invW[u + 2];

        float4 mn = ((const float4*)g_mean)[quad];
        float4 sg = ((const float4*)g_sig)[quad];
        float4 ga = ((const float4*)gamma)[quad];
        float4 be = ((const float4*)beta)[quad];
        float4 wt = ((const float4*)lbin)[quad];
        float4 Aq = make_float4(wt.x*ga.x, wt.y*ga.y, wt.z*ga.z, wt.w*ga.w);
        float4 Bq = make_float4(__fdividef((1.f-wt.x)*ga.x, sg.x+EPSF),
                                __fdividef((1.f-wt.y)*ga.y, sg.y+EPSF),
                                __fdividef((1.f-wt.z)*ga.z, sg.z+EPSF),
                                __fdividef((1.f-wt.w)*ga.w, sg.w+EPSF));
        float4 Dq = make_float4(be.x - Bq.x*mn.x, be.y - Bq.y*mn.y,
                                be.z - Bq.z*mn.z, be.w - Bq.w*mn.w);

        const float4* hcol = hx + u;
        float4* op = out4 + ((size_t)b * 16384 + (size_t)(oy + v0) * 128 + (ox + u)) * 32 + quad;
        float4 s = f4add(f4add(f4add(hcol[(v0+0)*37], hcol[(v0+1)*37]),
                               f4add(hcol[(v0+2)*37], hcol[(v0+3)*37])), hcol[(v0+4)*37]);
        #pragma unroll
        for (int it = 0; it < 8; ++it) {
            int v = v0 + it;
            s = f4add(s, hcol[(v + 5) * 37]);
            float ic = iw * invH[v + 2];
            float4 xv = sx[(v + 4) * 42 + (u + 4)];
            float4 nm = df[(v + 2) * 37 + (u + 2)];
            float4 o;
            o.x = Aq.x * __fdividef(nm.x, fmaf(s.x, ic, EPSF)) + fmaf(Bq.x, xv.x, Dq.x);
            o.y = Aq.y * __fdividef(nm.y, fmaf(s.y, ic, EPSF)) + fmaf(Bq.y, xv.y, Dq.y);
            o.z = Aq.z * __fdividef(nm.z, fmaf(s.z, ic, EPSF)) + fmaf(Bq.z, xv.z, Dq.z);
            o.w = Aq.w * __fdividef(nm.w, fmaf(s.w, ic, EPSF)) + fmaf(Bq.w, xv.w, Dq.w);
            op[(size_t)it * 4096] = o;   // +1 output row = 128*32 float4
            s = f4sub(s, hcol[v * 37]);
        }
    }
}

// ---------------- host ----------------
typedef CUresult (*EncodeTiledFn)(
    CUtensorMap*, CUtensorMapDataType, cuuint32_t, void*,
    const cuuint64_t*, const cuuint64_t*, const cuuint32_t*, const cuuint32_t*,
    CUtensorMapInterleave, CUtensorMapSwizzle, CUtensorMapL2promotion, CUtensorMapFloatOOBfill);

extern "C" void kernel_launch(void* const* d_in, const int* in_sizes, int n_in,
                              void* d_out, int out_size)
{
    (void)in_sizes; (void)n_in; (void)out_size;
    const float* x     = (const float*)d_in[0];
    const float* gamma = (const float*)d_in[1];
    const float* beta  = (const float*)d_in[2];
    const float* lbin  = (const float*)d_in[3];

    CUtensorMap tmin;
    int use_tma = 0;
    {
        EncodeTiledFn enc = nullptr;
        cudaDriverEntryPointQueryResult qr;
        if (cudaGetDriverEntryPoint("cuTensorMapEncodeTiled", (void**)&enc,
                                    cudaEnableDefault, &qr) == cudaSuccess && enc) {
            cuuint64_t dims[4]    = {128, 128, 128, 32};
            cuuint64_t strides[3] = {512, 65536, 8388608};   // bytes for dims 1..3
            cuuint32_t es[4]      = {1, 1, 1, 1};
            cuuint32_t box_in[4]  = {4, 42, 42, 1};
            CUresult r1 = enc(&tmin, CU_TENSOR_MAP_DATA_TYPE_FLOAT32, 4, (void*)x,
                              dims, strides, box_in, es,
                              CU_TENSOR_MAP_INTERLEAVE_NONE, CU_TENSOR_MAP_SWIZZLE_NONE,
                              CU_TENSOR_MAP_L2_PROMOTION_L2_128B, CU_TENSOR_MAP_FLOAT_OOB_FILL_NONE);
            use_tma = (r1 == CUDA_SUCCESS) ? 1 : 0;
        }
    }

    cudaFuncSetAttribute(k_main, cudaFuncAttributeMaxDynamicSharedMemorySize, SMEMB);

    const int n4 = (32 * 128 * 128 * 128) / 4;
    k_stats<<<SBLK, 256>>>((const float4*)x, n4);
    k_reduce<<<128, 128>>>();
    dim3 grid(32, 16, 32);
    k_main<<<grid, 256, SMEMB>>>(tmin, x, gamma, beta, lbin, (float4*)d_out, use_tma);
}

// round 15
// speedup vs baseline: 1.1630x; 1.1630x over previous
#include <cuda_runtime.h>
#include <cuda.h>
#include <cuda_fp16.h>
#include <cuda_bf16.h>
#include <cstdint>

#define EPSF 1e-5f
#define SBLK 592

// ---------------- device scratch ----------------
__device__ float g_part[SBLK * 384];   // [blk][stat(3)][chan(128)]
__device__ float g_mean[128];
__device__ float g_sig[128];

// ---------------- helpers ----------------
__device__ __forceinline__ float4 f4add(float4 a, float4 b) {
    return make_float4(a.x+b.x, a.y+b.y, a.z+b.z, a.w+b.w);
}
__device__ __forceinline__ float4 f4sub(float4 a, float4 b) {
    return make_float4(a.x-b.x, a.y-b.y, a.z-b.z, a.w-b.w);
}
__device__ __forceinline__ float4 f4zero() { return make_float4(0.f,0.f,0.f,0.f); }
__device__ __forceinline__ float cntf(int g) {
    int lo = g - 2 < 0 ? 0 : g - 2;
    int hi = g + 3 > 127 ? 127 : g + 3;
    return (float)(hi - lo + 1);
}
__device__ __forceinline__ uint32_t s2u(const void* p) {
    uint32_t a;
    asm("{ .reg .u64 t; cvta.to.shared.u64 t, %1; cvt.u32.u64 %0, t; }" : "=r"(a) : "l"(p));
    return a;
}
// pack float4 -> 2x half2 bits
__device__ __forceinline__ uint2 f4_to_h2x2(float4 v) {
    __half2 h0 = __floats2half2_rn(v.x, v.y);
    __half2 h1 = __floats2half2_rn(v.z, v.w);
    uint2 p;
    p.x = *reinterpret_cast<uint32_t*>(&h0);
    p.y = *reinterpret_cast<uint32_t*>(&h1);
    return p;
}
// unpack 2x half2 bits -> float4
__device__ __forceinline__ float4 h2x2_to_f4(uint2 p) {
    __half2 h0 = *reinterpret_cast<__half2*>(&p.x);
    __half2 h1 = *reinterpret_cast<__half2*>(&p.y);
    float2 f0 = __half22float2(h0);
    float2 f1 = __half22float2(h1);
    return make_float4(f0.x, f0.y, f1.x, f1.y);
}

#define MBAR_INIT(mb, cnt) \
    asm volatile("mbarrier.init.shared.b64 [%0], %1;" :: "r"(mb), "r"(cnt) : "memory")
#define MBAR_EXPECT_TX(mb, bytes) \
    asm volatile("mbarrier.arrive.expect_tx.shared.b64 _, [%0], %1;" :: "r"(mb), "r"(bytes) : "memory")
#define MBAR_WAIT(mb, ph) do { \
    uint32_t _done = 0; \
    asm volatile("{\n\t.reg .pred p;\n\tmbarrier.try_wait.parity.acquire.cta.shared::cta.b64 p, [%1], %2;\n\tselp.b32 %0, 1, 0, p;\n\t}" \
        : "=r"(_done) : "r"(mb), "r"(ph) : "memory"); \
    if (!_done) { \
        asm volatile("{\n\t.reg .pred P1;\n\tWL%=:\n\tmbarrier.try_wait.parity.acquire.cta.shared::cta.b64 P1, [%0], %1, 0x989680;\n\t@P1 bra.uni WD%=;\n\tbra.uni WL%=;\n\tWD%=:\n\t}" \
            :: "r"(mb), "r"(ph) : "memory"); \
    } } while (0)

// ---------------- kernel 1: per-block partial stats ----------------
__global__ __launch_bounds__(256, 4)
void k_stats(const float4* __restrict__ x4, int n4)
{
    __shared__ float sbuf[8][32][12];
    const int tx = threadIdx.x;
    const int wz = tx >> 5, gg = tx & 31;

    float s0=0,s1=0,s2=0,s3=0, a0=0,a1=0,a2=0,a3=0, q0=0,q1=0,q2=0,q3=0;
    const int stride = SBLK * 256;
    #pragma unroll 4
    for (int i = blockIdx.x * 256 + tx; i < n4; i += stride) {
        float4 v = x4[i];
        s0 += v.x; a0 += fabsf(v.x); q0 += (v.x > 0.f ? 1.f : -1.f);
        s1 += v.y; a1 += fabsf(v.y); q1 += (v.y > 0.f ? 1.f : -1.f);
        s2 += v.z; a2 += fabsf(v.z); q2 += (v.z > 0.f ? 1.f : -1.f);
        s3 += v.w; a3 += fabsf(v.w); q3 += (v.w > 0.f ? 1.f : -1.f);
    }
    sbuf[wz][gg][0]=s0; sbuf[wz][gg][1]=s1; sbuf[wz][gg][2]=s2;  sbuf[wz][gg][3]=s3;
    sbuf[wz][gg][4]=a0; sbuf[wz][gg][5]=a1; sbuf[wz][gg][6]=a2;  sbuf[wz][gg][7]=a3;
    sbuf[wz][gg][8]=q0; sbuf[wz][gg][9]=q1; sbuf[wz][gg][10]=q2; sbuf[wz][gg][11]=q3;
    __syncthreads();
    for (int o = tx; o < 384; o += 256) {
        int stat = o >> 7, c = o & 127;
        int g2 = c >> 2, j2 = c & 3;
        float t = 0.f;
        #pragma unroll
        for (int z = 0; z < 8; ++z) t += sbuf[z][g2][stat*4 + j2];
        g_part[blockIdx.x * 384 + o] = t;
    }
}

// ---------------- kernel 2: fold partials ----------------
__global__ void k_reduce()
{
    const int c = blockIdx.x;
    const int t = threadIdx.x;
    float s0=0.f, s1=0.f, s2=0.f;
    for (int blk = t; blk < SBLK; blk += 128) {
        const float* p = g_part + blk * 384;
        s0 += p[c]; s1 += p[128 + c]; s2 += p[256 + c];
    }
    __shared__ float r0[128], r1[128], r2[128];
    r0[t]=s0; r1[t]=s1; r2[t]=s2;
    __syncthreads();
    #pragma unroll
    for (int off = 64; off > 0; off >>= 1) {
        if (t < off) { r0[t]+=r0[t+off]; r1[t]+=r1[t+off]; r2[t]+=r2[t+off]; }
        __syncthreads();
    }
    if (t == 0) {
        const float invN = 1.f / (32.f * 128.f * 128.f);
        float m = r0[0] * invN;
        g_mean[c] = m;
        g_sig[c]  = (r1[0] - m * r2[0]) * invN;
    }
}

// ---------------- kernel 3: fused local mean/MAD/blend ----------------
// grid (32 quads, 16 tiles, 32 batch), 256 threads, 3 CTAs/SM.
// smem (bytes):
//   sx @ 0     : [42][42] float4 = 28224  (TMA load target)
//   hx @ 28288 : [42][37] float4 = 24864  (reused as hd[37][37] in stage C)
//   df @ 53248 : [37][37] uint2 (half2x2) = 10952; region padded to 16384 and
//                reused as ob[32][32] float4 (TMA store source, 128B-aligned)
#define N_SX (42*42)
#define OFF_SX 0
#define OFF_HX 28288
#define OFF_DF 53248
#define SMEMB (OFF_DF + 16384)

__global__ __launch_bounds__(256, 3)
void k_main(const __grid_constant__ CUtensorMap tmin,
            const __grid_constant__ CUtensorMap tmout,
            const float* __restrict__ x,
            const float* __restrict__ gamma,
            const float* __restrict__ beta,
            const float* __restrict__ lbin,
            float* __restrict__ out,
            int use_tma)
{
    extern __shared__ __align__(128) char smdyn[];
    float4* sx  = (float4*)(smdyn + OFF_SX);   // [42][42]
    float4* hx  = (float4*)(smdyn + OFF_HX);   // [42][37]
    uint2*  df  = (uint2*)(smdyn + OFF_DF);    // [37][37] half2x2
    float4* ob  = (float4*)(smdyn + OFF_DF);   // [32][32], reused after stage D compute

    __shared__ __align__(8) uint64_t mbar;
    __shared__ float invW[37], invH[37];

    const int tx = threadIdx.x;
    const int quad = blockIdx.x;
    const int ox = (blockIdx.y & 3) * 32;
    const int oy = (blockIdx.y >> 2) * 32;
    const int b  = blockIdx.z;

    const uint32_t mb = s2u(&mbar);

    if (tx == 0) MBAR_INIT(mb, 1);
    __syncthreads();

    if (use_tma) {
        if (tx == 0) {
            MBAR_EXPECT_TX(mb, (uint32_t)(N_SX * 16));
            asm volatile(
                "cp.async.bulk.tensor.4d.shared::cta.global.tile.mbarrier::complete_tx::bytes "
                "[%0], [%1, {%2, %3, %4, %5}], [%6];"
                :: "r"(s2u(sx)), "l"(&tmin),
                   "r"(quad * 4), "r"(ox - 4), "r"(oy - 4), "r"(b),
                   "r"(mb) : "memory");
        }
    } else {
        const float4* xb = (const float4*)x;
        for (int p = tx; p < N_SX; p += 256) {
            int iy = p / 42, ix = p - iy * 42;
            int gr = oy - 4 + iy, gc = ox - 4 + ix;
            float4 v = f4zero();
            if ((unsigned)gr < 128u && (unsigned)gc < 128u)
                v = xb[((size_t)b * 16384 + gr * 128 + gc) * 32 + quad];
            sx[p] = v;
        }
    }

    // inverse window counts (overlaps the load)
    if (tx >= 160 && tx < 234) {
        int k = tx - 160;
        if (k < 37) invW[k] = 1.f / cntf(ox - 2 + k);
        else        invH[k - 37] = 1.f / cntf(oy - 2 + (k - 37));
    }

    if (use_tma) { MBAR_WAIT(mb, 0); }
    else __syncthreads();

    // Stage A: horizontal 6-box of x. 252 threads: (row y, chunk of 7 outputs).
    // 12 contiguous register-cached reads/thread; lane addr step 112B -> conflict-free.
    if (tx < 252) {
        int y = tx / 6;
        int j0 = (tx % 6) * 7;
        const float4* row = sx + y * 42;
        float4 v[12];
        #pragma unroll
        for (int k = 0; k < 12; ++k)
            v[k] = (j0 + k <= 41) ? row[j0 + k] : f4zero();
        float4* hrow = hx + y * 37;
        float4 s = f4add(f4add(f4add(v[0], v[1]), f4add(v[2], v[3])), v[4]);
        #pragma unroll
        for (int k = 0; k < 7; ++k) {
            s = f4add(s, v[k + 5]);
            if (j0 + k <= 36) hrow[j0 + k] = s;
            s = f4sub(s, v[k]);
        }
    }
    __syncthreads();

    // Stage B: vertical 6-box -> local mean; df = x - lm (0 outside image), fp16-packed.
    // 148 threads: (col j, 4 segments of 10/9 rows). Lane-contiguous -> conflict-free.
    if (tx < 148) {
        int j = tx % 37, seg = tx / 37;
        int r0 = (seg == 0) ? 0 : (9 * seg + 1);
        int rn = (seg == 0) ? 10 : 9;
        float iw = invW[j];
        int gc = ox - 2 + j;
        bool cin = ((unsigned)gc < 128u);
        const float4* hcol = hx + j;
        float4 s = f4add(f4add(f4add(hcol[(r0+0)*37], hcol[(r0+1)*37]),
                               f4add(hcol[(r0+2)*37], hcol[(r0+3)*37])), hcol[(r0+4)*37]);
        #pragma unroll 5
        for (int it = 0; it < rn; ++it) {
            int r = r0 + it;
            s = f4add(s, hcol[(r + 5) * 37]);
            int gr = oy - 2 + r;
            float ic = iw * invH[r];
            float4 xv = sx[(r + 2) * 42 + (j + 2)];
            float4 dv = f4zero();
            if (cin && (unsigned)gr < 128u) {
                dv.x = xv.x - s.x * ic;
                dv.y = xv.y - s.y * ic;
                dv.z = xv.z - s.z * ic;
                dv.w = xv.w - s.w * ic;
            }
            df[r * 37 + j] = f4_to_h2x2(dv);
            s = f4sub(s, hcol[r * 37]);
        }
    }
    __syncthreads();

    // Stage C: horizontal 6-box of |df| -> hd (reuses hx). 185 threads:
    // (row r = tx%37 lane-fast; chunk of 7 outputs). |.| done by sign-mask on packed bits.
    if (tx < 185) {
        int r = tx % 37;
        int u0 = (tx / 37) * 7;
        const uint2* drow = df + r * 37;
        float4 v[12];
        #pragma unroll
        for (int k = 0; k < 12; ++k) {
            if (u0 + k <= 36) {
                uint2 p = drow[u0 + k];
                p.x &= 0x7FFF7FFFu;
                p.y &= 0x7FFF7FFFu;
                v[k] = h2x2_to_f4(p);
            } else {
                v[k] = f4zero();
            }
        }
        float4* hrow = hx + r * 37;
        float4 s = f4add(f4add(f4add(v[0], v[1]), f4add(v[2], v[3])), v[4]);
        #pragma unroll
        for (int k = 0; k < 7; ++k) {
            s = f4add(s, v[k + 5]);
            if (u0 + k <= 31) hrow[u0 + k] = s;
            s = f4sub(s, v[k]);
        }
    }
    __syncthreads();

    // Stage D: vertical 6-box of hd -> mad; blend + affine.
    // 128 threads: (col u, 4 segments of 8 rows). Lane-contiguous -> conflict-free.
    float4 o[8];
    if (tx < 128) {
        int u = tx & 31, seg = tx >> 5;
        int v0 = seg * 8;
        float iw = invW[u + 2];

        float4 mn = ((const float4*)g_mean)[quad];
        float4 sg = ((const float4*)g_sig)[quad];
        float4 ga = ((const float4*)gamma)[quad];
        float4 be = ((const float4*)beta)[quad];
        float4 wt = ((const float4*)lbin)[quad];
        float4 Aq = make_float4(wt.x*ga.x, wt.y*ga.y, wt.z*ga.z, wt.w*ga.w);
        float4 Bq = make_float4(__fdividef((1.f-wt.x)*ga.x, sg.x+EPSF),
                                __fdividef((1.f-wt.y)*ga.y, sg.y+EPSF),
                                __fdividef((1.f-wt.z)*ga.z, sg.z+EPSF),
                                __fdividef((1.f-wt.w)*ga.w, sg.w+EPSF));
        float4 Dq = make_float4(be.x - Bq.x*mn.x, be.y - Bq.y*mn.y,
                                be.z - Bq.z*mn.z, be.w - Bq.w*mn.w);

        const float4* hcol = hx + u;
        float4 s = f4add(f4add(f4add(hcol[(v0+0)*37], hcol[(v0+1)*37]),
                               f4add(hcol[(v0+2)*37], hcol[(v0+3)*37])), hcol[(v0+4)*37]);
        #pragma unroll
        for (int it = 0; it < 8; ++it) {
            int v = v0 + it;
            s = f4add(s, hcol[(v + 5) * 37]);
            float ic = iw * invH[v + 2];
            float4 xv = sx[(v + 4) * 42 + (u + 4)];
            float4 nm = h2x2_to_f4(df[(v + 2) * 37 + (u + 2)]);
            o[it].x = Aq.x * __fdividef(nm.x, fmaf(s.x, ic, EPSF)) + fmaf(Bq.x, xv.x, Dq.x);
            o[it].y = Aq.y * __fdividef(nm.y, fmaf(s.y, ic, EPSF)) + fmaf(Bq.y, xv.y, Dq.y);
            o[it].z = Aq.z * __fdividef(nm.z, fmaf(s.z, ic, EPSF)) + fmaf(Bq.z, xv.z, Dq.z);
            o[it].w = Aq.w * __fdividef(nm.w, fmaf(s.w, ic, EPSF)) + fmaf(Bq.w, xv.w, Dq.w);
            s = f4sub(s, hcol[v * 37]);
        }
    }
    __syncthreads();   // all df reads done; safe to overwrite with ob
    if (tx < 128) {
        int u = tx & 31, v0 = (tx >> 5) * 8;
        #pragma unroll
        for (int it = 0; it < 8; ++it)
            ob[(v0 + it) * 32 + u] = o[it];
    }
    __syncthreads();

    if (use_tma) {
        if (tx == 0) {
            asm volatile("fence.proxy.async.shared::cta;" ::: "memory");
            asm volatile(
                "cp.async.bulk.tensor.4d.global.shared::cta.tile.bulk_group "
                "[%0, {%1, %2, %3, %4}], [%5];"
                :: "l"(&tmout), "r"(quad * 4), "r"(ox), "r"(oy), "r"(b), "r"(s2u(ob))
                : "memory");
            asm volatile("cp.async.bulk.commit_group;" ::: "memory");
            asm volatile("cp.async.bulk.wait_group 0;" ::: "memory");
        }
    } else {
        float4* op = (float4*)out;
        for (int p = tx; p < 1024; p += 256) {
            int v = p >> 5, u = p & 31;
            op[((size_t)b * 16384 + (oy + v) * 128 + (ox + u)) * 32 + quad] = ob[p];
        }
    }
}

// ---------------- host ----------------
typedef CUresult (*EncodeTiledFn)(
    CUtensorMap*, CUtensorMapDataType, cuuint32_t, void*,
    const cuuint64_t*, const cuuint64_t*, const cuuint32_t*, const cuuint32_t*,
    CUtensorMapInterleave, CUtensorMapSwizzle, CUtensorMapL2promotion, CUtensorMapFloatOOBfill);

extern "C" void kernel_launch(void* const* d_in, const int* in_sizes, int n_in,
                              void* d_out, int out_size)
{
    (void)in_sizes; (void)n_in; (void)out_size;
    const float* x     = (const float*)d_in[0];
    const float* gamma = (const float*)d_in[1];
    const float* beta  = (const float*)d_in[2];
    const float* lbin  = (const float*)d_in[3];
    float* out = (float*)d_out;

    CUtensorMap tmin, tmout;
    int use_tma = 0;
    {
        EncodeTiledFn enc = nullptr;
        cudaDriverEntryPointQueryResult qr;
        if (cudaGetDriverEntryPoint("cuTensorMapEncodeTiled", (void**)&enc,
                                    cudaEnableDefault, &qr) == cudaSuccess && enc) {
            cuuint64_t dims[4]    = {128, 128, 128, 32};
            cuuint64_t strides[3] = {512, 65536, 8388608};   // bytes for dims 1..3
            cuuint32_t es[4]      = {1, 1, 1, 1};
            cuuint32_t box_in[4]  = {4, 42, 42, 1};
            cuuint32_t box_out[4] = {4, 32, 32, 1};
            CUresult r1 = enc(&tmin, CU_TENSOR_MAP_DATA_TYPE_FLOAT32, 4, (void*)x,
                              dims, strides, box_in, es,
                              CU_TENSOR_MAP_INTERLEAVE_NONE, CU_TENSOR_MAP_SWIZZLE_NONE,
                              CU_TENSOR_MAP_L2_PROMOTION_L2_128B, CU_TENSOR_MAP_FLOAT_OOB_FILL_NONE);
            CUresult r2 = enc(&tmout, CU_TENSOR_MAP_DATA_TYPE_FLOAT32, 4, (void*)d_out,
                              dims, strides, box_out, es,
                              CU_TENSOR_MAP_INTERLEAVE_NONE, CU_TENSOR_MAP_SWIZZLE_NONE,
                              CU_TENSOR_MAP_L2_PROMOTION_L2_128B, CU_TENSOR_MAP_FLOAT_OOB_FILL_NONE);
            use_tma = (r1 == CUDA_SUCCESS && r2 == CUDA_SUCCESS) ? 1 : 0;
        }
    }

    cudaFuncSetAttribute(k_main, cudaFuncAttributeMaxDynamicSharedMemorySize, SMEMB);

    const int n4 = (32 * 128 * 128 * 128) / 4;
    k_stats<<<SBLK, 256>>>((const float4*)x, n4);
    k_reduce<<<128, 128>>>();
    dim3 grid(32, 16, 32);
    k_main<<<grid, 256, SMEMB>>>(tmin, tmout, x, gamma, beta, lbin, out, use_tma);
}

// round 16
// speedup vs baseline: 1.2280x; 1.0559x over previous
#include <cuda_runtime.h>
#include <cuda.h>
#include <cuda_fp16.h>
#include <cuda_bf16.h>
#include <cstdint>

#define EPSF 1e-5f
#define SBLK 592

// ---------------- device scratch ----------------
__device__ float g_part[SBLK * 384];   // [blk][stat(3)][chan(128)]
__device__ float g_mean[128];
__device__ float g_sig[128];

// ---------------- helpers ----------------
__device__ __forceinline__ float4 f4add(float4 a, float4 b) {
    return make_float4(a.x+b.x, a.y+b.y, a.z+b.z, a.w+b.w);
}
__device__ __forceinline__ float4 f4sub(float4 a, float4 b) {
    return make_float4(a.x-b.x, a.y-b.y, a.z-b.z, a.w-b.w);
}
__device__ __forceinline__ float4 f4zero() { return make_float4(0.f,0.f,0.f,0.f); }
__device__ __forceinline__ float cntf(int g) {
    int lo = g - 2 < 0 ? 0 : g - 2;
    int hi = g + 3 > 127 ? 127 : g + 3;
    return (float)(hi - lo + 1);
}
__device__ __forceinline__ uint32_t s2u(const void* p) {
    uint32_t a;
    asm("{ .reg .u64 t; cvta.to.shared.u64 t, %1; cvt.u32.u64 %0, t; }" : "=r"(a) : "l"(p));
    return a;
}
// pack float4 -> 2x half2 bits
__device__ __forceinline__ uint2 f4_to_h2x2(float4 v) {
    __half2 h0 = __floats2half2_rn(v.x, v.y);
    __half2 h1 = __floats2half2_rn(v.z, v.w);
    uint2 p;
    p.x = *reinterpret_cast<uint32_t*>(&h0);
    p.y = *reinterpret_cast<uint32_t*>(&h1);
    return p;
}
// unpack 2x half2 bits -> float4
__device__ __forceinline__ float4 h2x2_to_f4(uint2 p) {
    __half2 h0 = *reinterpret_cast<__half2*>(&p.x);
    __half2 h1 = *reinterpret_cast<__half2*>(&p.y);
    float2 f0 = __half22float2(h0);
    float2 f1 = __half22float2(h1);
    return make_float4(f0.x, f0.y, f1.x, f1.y);
}

#define MBAR_INIT(mb, cnt) \
    asm volatile("mbarrier.init.shared.b64 [%0], %1;" :: "r"(mb), "r"(cnt) : "memory")
#define MBAR_EXPECT_TX(mb, bytes) \
    asm volatile("mbarrier.arrive.expect_tx.shared.b64 _, [%0], %1;" :: "r"(mb), "r"(bytes) : "memory")
#define MBAR_WAIT(mb, ph) do { \
    uint32_t _done = 0; \
    asm volatile("{\n\t.reg .pred p;\n\tmbarrier.try_wait.parity.acquire.cta.shared::cta.b64 p, [%1], %2;\n\tselp.b32 %0, 1, 0, p;\n\t}" \
        : "=r"(_done) : "r"(mb), "r"(ph) : "memory"); \
    if (!_done) { \
        asm volatile("{\n\t.reg .pred P1;\n\tWL%=:\n\tmbarrier.try_wait.parity.acquire.cta.shared::cta.b64 P1, [%0], %1, 0x989680;\n\t@P1 bra.uni WD%=;\n\tbra.uni WL%=;\n\tWD%=:\n\t}" \
            :: "r"(mb), "r"(ph) : "memory"); \
    } } while (0)

// ---------------- kernel 1: per-block partial stats ----------------
__global__ __launch_bounds__(256, 4)
void k_stats(const float4* __restrict__ x4, int n4)
{
    __shared__ float sbuf[8][32][12];
    const int tx = threadIdx.x;
    const int wz = tx >> 5, gg = tx & 31;

    float s0=0,s1=0,s2=0,s3=0, a0=0,a1=0,a2=0,a3=0, q0=0,q1=0,q2=0,q3=0;
    const int stride = SBLK * 256;
    #pragma unroll 4
    for (int i = blockIdx.x * 256 + tx; i < n4; i += stride) {
        float4 v = x4[i];
        s0 += v.x; a0 += fabsf(v.x); q0 += (v.x > 0.f ? 1.f : -1.f);
        s1 += v.y; a1 += fabsf(v.y); q1 += (v.y > 0.f ? 1.f : -1.f);
        s2 += v.z; a2 += fabsf(v.z); q2 += (v.z > 0.f ? 1.f : -1.f);
        s3 += v.w; a3 += fabsf(v.w); q3 += (v.w > 0.f ? 1.f : -1.f);
    }
    sbuf[wz][gg][0]=s0; sbuf[wz][gg][1]=s1; sbuf[wz][gg][2]=s2;  sbuf[wz][gg][3]=s3;
    sbuf[wz][gg][4]=a0; sbuf[wz][gg][5]=a1; sbuf[wz][gg][6]=a2;  sbuf[wz][gg][7]=a3;
    sbuf[wz][gg][8]=q0; sbuf[wz][gg][9]=q1; sbuf[wz][gg][10]=q2; sbuf[wz][gg][11]=q3;
    __syncthreads();
    for (int o = tx; o < 384; o += 256) {
        int stat = o >> 7, c = o & 127;
        int g2 = c >> 2, j2 = c & 3;
        float t = 0.f;
        #pragma unroll
        for (int z = 0; z < 8; ++z) t += sbuf[z][g2][stat*4 + j2];
        g_part[blockIdx.x * 384 + o] = t;
    }
}

// ---------------- kernel 2: fold partials ----------------
__global__ void k_reduce()
{
    const int c = blockIdx.x;
    const int t = threadIdx.x;
    float s0=0.f, s1=0.f, s2=0.f;
    for (int blk = t; blk < SBLK; blk += 128) {
        const float* p = g_part + blk * 384;
        s0 += p[c]; s1 += p[128 + c]; s2 += p[256 + c];
    }
    __shared__ float r0[128], r1[128], r2[128];
    r0[t]=s0; r1[t]=s1; r2[t]=s2;
    __syncthreads();
    #pragma unroll
    for (int off = 64; off > 0; off >>= 1) {
        if (t < off) { r0[t]+=r0[t+off]; r1[t]+=r1[t+off]; r2[t]+=r2[t+off]; }
        __syncthreads();
    }
    if (t == 0) {
        const float invN = 1.f / (32.f * 128.f * 128.f);
        float m = r0[0] * invN;
        g_mean[c] = m;
        g_sig[c]  = (r1[0] - m * r2[0]) * invN;
    }
}

// ---------------- kernel 3: fused local mean/MAD/blend ----------------
// grid (32 quads, 16 tiles, 32 batch), 256 threads, 4 CTAs/SM.
// smem (bytes):
//   sx @ 0     : [42][42] float4 = 28224  (TMA load target), pad -> 28288
//   hx @ 28288 : [42][37] uint2 (half2x2) = 12432, pad -> 12544 (ends 40832)
//   df @ 40832 : [37][37] uint2 (half2x2) = 10952 (ends 51784)
//   ob @ 28288 : [32][32] float4 = 16384 — aliases hx + head of df, both dead
//                after stage D's register compute (barrier-separated).
#define N_SX (42*42)
#define OFF_SX 0
#define OFF_HX 28288
#define OFF_DF 40832
#define OFF_OB 28288
#define SMEMB 51840

__global__ __launch_bounds__(256, 4)
void k_main(const __grid_constant__ CUtensorMap tmin,
            const __grid_constant__ CUtensorMap tmout,
            const float* __restrict__ x,
            const float* __restrict__ gamma,
            const float* __restrict__ beta,
            const float* __restrict__ lbin,
            float* __restrict__ out,
            int use_tma)
{
    extern __shared__ __align__(128) char smdyn[];
    float4* sx  = (float4*)(smdyn + OFF_SX);   // [42][42] fp32
    uint2*  hxh = (uint2*)(smdyn + OFF_HX);    // [42][37] half2x2 (reused as hd in C)
    uint2*  df  = (uint2*)(smdyn + OFF_DF);    // [37][37] half2x2
    float4* ob  = (float4*)(smdyn + OFF_OB);   // [32][32] fp32, aliases hx/df after D

    __shared__ __align__(8) uint64_t mbar;
    __shared__ float invW[37], invH[37];

    const int tx = threadIdx.x;
    const int quad = blockIdx.x;
    const int ox = (blockIdx.y & 3) * 32;
    const int oy = (blockIdx.y >> 2) * 32;
    const int b  = blockIdx.z;

    const uint32_t mb = s2u(&mbar);

    if (tx == 0) MBAR_INIT(mb, 1);
    __syncthreads();

    if (use_tma) {
        if (tx == 0) {
            MBAR_EXPECT_TX(mb, (uint32_t)(N_SX * 16));
            asm volatile(
                "cp.async.bulk.tensor.4d.shared::cta.global.tile.mbarrier::complete_tx::bytes "
                "[%0], [%1, {%2, %3, %4, %5}], [%6];"
                :: "r"(s2u(sx)), "l"(&tmin),
                   "r"(quad * 4), "r"(ox - 4), "r"(oy - 4), "r"(b),
                   "r"(mb) : "memory");
        }
    } else {
        const float4* xb = (const float4*)x;
        for (int p = tx; p < N_SX; p += 256) {
            int iy = p / 42, ix = p - iy * 42;
            int gr = oy - 4 + iy, gc = ox - 4 + ix;
            float4 v = f4zero();
            if ((unsigned)gr < 128u && (unsigned)gc < 128u)
                v = xb[((size_t)b * 16384 + gr * 128 + gc) * 32 + quad];
            sx[p] = v;
        }
    }

    // inverse window counts (overlaps the load)
    if (tx >= 160 && tx < 234) {
        int k = tx - 160;
        if (k < 37) invW[k] = 1.f / cntf(ox - 2 + k);
        else        invH[k - 37] = 1.f / cntf(oy - 2 + (k - 37));
    }

    if (use_tma) { MBAR_WAIT(mb, 0); }
    else __syncthreads();

    // Stage A: horizontal 6-box of x -> hx (fp16 packed). 252 threads:
    // (row y, chunk of 7 outputs). 12 contiguous fp32 reads/thread; conflict-free.
    if (tx < 252) {
        int y = tx / 6;
        int j0 = (tx % 6) * 7;
        const float4* row = sx + y * 42;
        float4 v[12];
        #pragma unroll
        for (int k = 0; k < 12; ++k)
            v[k] = (j0 + k <= 41) ? row[j0 + k] : f4zero();
        uint2* hrow = hxh + y * 37;
        float4 s = f4add(f4add(f4add(v[0], v[1]), f4add(v[2], v[3])), v[4]);
        #pragma unroll
        for (int k = 0; k < 7; ++k) {
            s = f4add(s, v[k + 5]);
            if (j0 + k <= 36) hrow[j0 + k] = f4_to_h2x2(s);
            s = f4sub(s, v[k]);
        }
    }
    __syncthreads();

    // Stage B: vertical 6-box -> local mean; df = x - lm (0 outside image), fp16.
    // 148 threads: (col j, 4 segments of 10/9 rows). Running sum in fp32;
    // enter/exit reads load identical fp16 bits -> exact cancellation.
    if (tx < 148) {
        int j = tx % 37, seg = tx / 37;
        int r0 = (seg == 0) ? 0 : (9 * seg + 1);
        int rn = (seg == 0) ? 10 : 9;
        float iw = invW[j];
        int gc = ox - 2 + j;
        bool cin = ((unsigned)gc < 128u);
        const uint2* hcol = hxh + j;
        float4 s = f4zero();
        #pragma unroll
        for (int k = 0; k < 5; ++k)
            s = f4add(s, h2x2_to_f4(hcol[(r0 + k) * 37]));
        #pragma unroll 5
        for (int it = 0; it < rn; ++it) {
            int r = r0 + it;
            s = f4add(s, h2x2_to_f4(hcol[(r + 5) * 37]));
            int gr = oy - 2 + r;
            float ic = iw * invH[r];
            float4 xv = sx[(r + 2) * 42 + (j + 2)];
            float4 dv = f4zero();
            if (cin && (unsigned)gr < 128u) {
                dv.x = xv.x - s.x * ic;
                dv.y = xv.y - s.y * ic;
                dv.z = xv.z - s.z * ic;
                dv.w = xv.w - s.w * ic;
            }
            df[r * 37 + j] = f4_to_h2x2(dv);
            s = f4sub(s, h2x2_to_f4(hcol[r * 37]));
        }
    }
    __syncthreads();

    // Stage C: horizontal 6-box of |df| -> hd (reuses hx region, fp16). 185 threads:
    // (row r = tx%37 lane-fast; chunk of 7 outputs). |.| via sign-mask on packed bits.
    if (tx < 185) {
        int r = tx % 37;
        int u0 = (tx / 37) * 7;
        const uint2* drow = df + r * 37;
        float4 v[12];
        #pragma unroll
        for (int k = 0; k < 12; ++k) {
            if (u0 + k <= 36) {
                uint2 p = drow[u0 + k];
                p.x &= 0x7FFF7FFFu;
                p.y &= 0x7FFF7FFFu;
                v[k] = h2x2_to_f4(p);
            } else {
                v[k] = f4zero();
            }
        }
        uint2* hrow = hxh + r * 37;
        float4 s = f4add(f4add(f4add(v[0], v[1]), f4add(v[2], v[3])), v[4]);
        #pragma unroll
        for (int k = 0; k < 7; ++k) {
            s = f4add(s, v[k + 5]);
            if (u0 + k <= 31) hrow[u0 + k] = f4_to_h2x2(s);
            s = f4sub(s, v[k]);
        }
    }
    __syncthreads();

    // Stage D: vertical 6-box of hd -> mad; blend + affine.
    // 128 threads: (col u, 4 segments of 8 rows). fp32 running sum over fp16 hd.
    float4 o[8];
    if (tx < 128) {
        int u = tx & 31, seg = tx >> 5;
        int v0 = seg * 8;
        float iw = invW[u + 2];

        float4 mn = ((const float4*)g_mean)[quad];
        float4 sg = ((const float4*)g_sig)[quad];
        float4 ga = ((const float4*)gamma)[quad];
        float4 be = ((const float4*)beta)[quad];
        float4 wt = ((const float4*)lbin)[quad];
        float4 Aq = make_float4(wt.x*ga.x, wt.y*ga.y, wt.z*ga.z, wt.w*ga.w);
        float4 Bq = make_float4(__fdividef((1.f-wt.x)*ga.x, sg.x+EPSF),
                                __fdividef((1.f-wt.y)*ga.y, sg.y+EPSF),
                                __fdividef((1.f-wt.z)*ga.z, sg.z+EPSF),
                                __fdividef((1.f-wt.w)*ga.w, sg.w+EPSF));
        float4 Dq = make_float4(be.x - Bq.x*mn.x, be.y - Bq.y*mn.y,
                                be.z - Bq.z*mn.z, be.w - Bq.w*mn.w);

        const uint2* hcol = hxh + u;
        float4 s = f4zero();
        #pragma unroll
        for (int k = 0; k < 5; ++k)
            s = f4add(s, h2x2_to_f4(hcol[(v0 + k) * 37]));
        #pragma unroll
        for (int it = 0; it < 8; ++it) {
            int v = v0 + it;
            s = f4add(s, h2x2_to_f4(hcol[(v + 5) * 37]));
            float ic = iw * invH[v + 2];
            float4 xv = sx[(v + 4) * 42 + (u + 4)];
            float4 nm = h2x2_to_f4(df[(v + 2) * 37 + (u + 2)]);
            o[it].x = Aq.x * __fdividef(nm.x, fmaf(s.x, ic, EPSF)) + fmaf(Bq.x, xv.x, Dq.x);
            o[it].y = Aq.y * __fdividef(nm.y, fmaf(s.y, ic, EPSF)) + fmaf(Bq.y, xv.y, Dq.y);
            o[it].z = Aq.z * __fdividef(nm.z, fmaf(s.z, ic, EPSF)) + fmaf(Bq.z, xv.z, Dq.z);
            o[it].w = Aq.w * __fdividef(nm.w, fmaf(s.w, ic, EPSF)) + fmaf(Bq.w, xv.w, Dq.w);
            s = f4sub(s, h2x2_to_f4(hcol[v * 37]));
        }
    }
    __syncthreads();   // all hx/df reads done; safe to overwrite with ob
    if (tx < 128) {
        int u = tx & 31, v0 = (tx >> 5) * 8;
        #pragma unroll
        for (int it = 0; it < 8; ++it)
            ob[(v0 + it) * 32 + u] = o[it];
    }
    __syncthreads();

    if (use_tma) {
        if (tx == 0) {
            asm volatile("fence.proxy.async.shared::cta;" ::: "memory");
            asm volatile(
                "cp.async.bulk.tensor.4d.global.shared::cta.tile.bulk_group "
                "[%0, {%1, %2, %3, %4}], [%5];"
                :: "l"(&tmout), "r"(quad * 4), "r"(ox), "r"(oy), "r"(b), "r"(s2u(ob))
                : "memory");
            asm volatile("cp.async.bulk.commit_group;" ::: "memory");
            asm volatile("cp.async.bulk.wait_group 0;" ::: "memory");
        }
    } else {
        float4* op = (float4*)out;
        for (int p = tx; p < 1024; p += 256) {
            int v = p >> 5, u = p & 31;
            op[((size_t)b * 16384 + (oy + v) * 128 + (ox + u)) * 32 + quad] = ob[p];
        }
    }
}

// ---------------- host ----------------
typedef CUresult (*EncodeTiledFn)(
    CUtensorMap*, CUtensorMapDataType, cuuint32_t, void*,
    const cuuint64_t*, const cuuint64_t*, const cuuint32_t*, const cuuint32_t*,
    CUtensorMapInterleave, CUtensorMapSwizzle, CUtensorMapL2promotion, CUtensorMapFloatOOBfill);

extern "C" void kernel_launch(void* const* d_in, const int* in_sizes, int n_in,
                              void* d_out, int out_size)
{
    (void)in_sizes; (void)n_in; (void)out_size;
    const float* x     = (const float*)d_in[0];
    const float* gamma = (const float*)d_in[1];
    const float* beta  = (const float*)d_in[2];
    const float* lbin  = (const float*)d_in[3];
    float* out = (float*)d_out;

    CUtensorMap tmin, tmout;
    int use_tma = 0;
    {
        EncodeTiledFn enc = nullptr;
        cudaDriverEntryPointQueryResult qr;
        if (cudaGetDriverEntryPoint("cuTensorMapEncodeTiled", (void**)&enc,
                                    cudaEnableDefault, &qr) == cudaSuccess && enc) {
            cuuint64_t dims[4]    = {128, 128, 128, 32};
            cuuint64_t strides[3] = {512, 65536, 8388608};   // bytes for dims 1..3
            cuuint32_t es[4]      = {1, 1, 1, 1};
            cuuint32_t box_in[4]  = {4, 42, 42, 1};
            cuuint32_t box_out[4] = {4, 32, 32, 1};
            CUresult r1 = enc(&tmin, CU_TENSOR_MAP_DATA_TYPE_FLOAT32, 4, (void*)x,
                              dims, strides, box_in, es,
                              CU_TENSOR_MAP_INTERLEAVE_NONE, CU_TENSOR_MAP_SWIZZLE_NONE,
                              CU_TENSOR_MAP_L2_PROMOTION_L2_128B, CU_TENSOR_MAP_FLOAT_OOB_FILL_NONE);
            CUresult r2 = enc(&tmout, CU_TENSOR_MAP_DATA_TYPE_FLOAT32, 4, (void*)d_out,
                              dims, strides, box_out, es,
                              CU_TENSOR_MAP_INTERLEAVE_NONE, CU_TENSOR_MAP_SWIZZLE_NONE,
                              CU_TENSOR_MAP_L2_PROMOTION_L2_128B, CU_TENSOR_MAP_FLOAT_OOB_FILL_NONE);
            use_tma = (r1 == CUDA_SUCCESS && r2 == CUDA_SUCCESS) ? 1 : 0;
        }
    }

    cudaFuncSetAttribute(k_main, cudaFuncAttributeMaxDynamicSharedMemorySize, SMEMB);

    const int n4 = (32 * 128 * 128 * 128) / 4;
    k_stats<<<SBLK, 256>>>((const float4*)x, n4);
    k_reduce<<<128, 128>>>();
    dim3 grid(32, 16, 32);
    k_main<<<grid, 256, SMEMB>>>(tmin, tmout, x, gamma, beta, lbin, out, use_tma);
}

// round 17
// speedup vs baseline: 1.3674x; 1.1136x over previous
#include <cuda_runtime.h>
#include <cuda.h>
#include <cuda_fp16.h>
#include <cuda_bf16.h>
#include <cstdint>

#define EPSF 1e-5f
#define SBLK 592

// ---------------- device scratch ----------------
__device__ float g_part[SBLK * 384];   // [blk][stat(3)][chan(128)]
__device__ float g_mean[128];
__device__ float g_sig[128];

// ---------------- helpers ----------------
__device__ __forceinline__ float4 f4add(float4 a, float4 b) {
    return make_float4(a.x+b.x, a.y+b.y, a.z+b.z, a.w+b.w);
}
__device__ __forceinline__ float4 f4sub(float4 a, float4 b) {
    return make_float4(a.x-b.x, a.y-b.y, a.z-b.z, a.w-b.w);
}
__device__ __forceinline__ float4 f4zero() { return make_float4(0.f,0.f,0.f,0.f); }
__device__ __forceinline__ float cntf(int g) {
    int lo = g - 2 < 0 ? 0 : g - 2;
    int hi = g + 3 > 127 ? 127 : g + 3;
    return (float)(hi - lo + 1);
}
__device__ __forceinline__ uint32_t s2u(const void* p) {
    uint32_t a;
    asm("{ .reg .u64 t; cvta.to.shared.u64 t, %1; cvt.u32.u64 %0, t; }" : "=r"(a) : "l"(p));
    return a;
}
// pack float4 -> 2x half2 bits
__device__ __forceinline__ uint2 f4_to_h2x2(float4 v) {
    __half2 h0 = __floats2half2_rn(v.x, v.y);
    __half2 h1 = __floats2half2_rn(v.z, v.w);
    uint2 p;
    p.x = *reinterpret_cast<uint32_t*>(&h0);
    p.y = *reinterpret_cast<uint32_t*>(&h1);
    return p;
}
// unpack 2x half2 bits -> float4
__device__ __forceinline__ float4 h2x2_to_f4(uint2 p) {
    __half2 h0 = *reinterpret_cast<__half2*>(&p.x);
    __half2 h1 = *reinterpret_cast<__half2*>(&p.y);
    float2 f0 = __half22float2(h0);
    float2 f1 = __half22float2(h1);
    return make_float4(f0.x, f0.y, f1.x, f1.y);
}

#define MBAR_INIT(mb, cnt) \
    asm volatile("mbarrier.init.shared.b64 [%0], %1;" :: "r"(mb), "r"(cnt) : "memory")
#define MBAR_EXPECT_TX(mb, bytes) \
    asm volatile("mbarrier.arrive.expect_tx.shared.b64 _, [%0], %1;" :: "r"(mb), "r"(bytes) : "memory")
#define MBAR_WAIT(mb, ph) do { \
    uint32_t _done = 0; \
    asm volatile("{\n\t.reg .pred p;\n\tmbarrier.try_wait.parity.acquire.cta.shared::cta.b64 p, [%1], %2;\n\tselp.b32 %0, 1, 0, p;\n\t}" \
        : "=r"(_done) : "r"(mb), "r"(ph) : "memory"); \
    if (!_done) { \
        asm volatile("{\n\t.reg .pred P1;\n\tWL%=:\n\tmbarrier.try_wait.parity.acquire.cta.shared::cta.b64 P1, [%0], %1, 0x989680;\n\t@P1 bra.uni WD%=;\n\tbra.uni WL%=;\n\tWD%=:\n\t}" \
            :: "r"(mb), "r"(ph) : "memory"); \
    } } while (0)

// ---------------- kernel 1: per-block partial stats ----------------
__global__ __launch_bounds__(256, 4)
void k_stats(const float4* __restrict__ x4, int n4)
{
    __shared__ float sbuf[8][32][12];
    const int tx = threadIdx.x;
    const int wz = tx >> 5, gg = tx & 31;

    float s0=0,s1=0,s2=0,s3=0, a0=0,a1=0,a2=0,a3=0, q0=0,q1=0,q2=0,q3=0;
    const int stride = SBLK * 256;
    #pragma unroll 4
    for (int i = blockIdx.x * 256 + tx; i < n4; i += stride) {
        float4 v = x4[i];
        s0 += v.x; a0 += fabsf(v.x); q0 += (v.x > 0.f ? 1.f : -1.f);
        s1 += v.y; a1 += fabsf(v.y); q1 += (v.y > 0.f ? 1.f : -1.f);
        s2 += v.z; a2 += fabsf(v.z); q2 += (v.z > 0.f ? 1.f : -1.f);
        s3 += v.w; a3 += fabsf(v.w); q3 += (v.w > 0.f ? 1.f : -1.f);
    }
    sbuf[wz][gg][0]=s0; sbuf[wz][gg][1]=s1; sbuf[wz][gg][2]=s2;  sbuf[wz][gg][3]=s3;
    sbuf[wz][gg][4]=a0; sbuf[wz][gg][5]=a1; sbuf[wz][gg][6]=a2;  sbuf[wz][gg][7]=a3;
    sbuf[wz][gg][8]=q0; sbuf[wz][gg][9]=q1; sbuf[wz][gg][10]=q2; sbuf[wz][gg][11]=q3;
    __syncthreads();
    for (int o = tx; o < 384; o += 256) {
        int stat = o >> 7, c = o & 127;
        int g2 = c >> 2, j2 = c & 3;
        float t = 0.f;
        #pragma unroll
        for (int z = 0; z < 8; ++z) t += sbuf[z][g2][stat*4 + j2];
        g_part[blockIdx.x * 384 + o] = t;
    }
}

// ---------------- kernel 2: fold partials ----------------
__global__ void k_reduce()
{
    const int c = blockIdx.x;
    const int t = threadIdx.x;
    float s0=0.f, s1=0.f, s2=0.f;
    for (int blk = t; blk < SBLK; blk += 128) {
        const float* p = g_part + blk * 384;
        s0 += p[c]; s1 += p[128 + c]; s2 += p[256 + c];
    }
    __shared__ float r0[128], r1[128], r2[128];
    r0[t]=s0; r1[t]=s1; r2[t]=s2;
    __syncthreads();
    #pragma unroll
    for (int off = 64; off > 0; off >>= 1) {
        if (t < off) { r0[t]+=r0[t+off]; r1[t]+=r1[t+off]; r2[t]+=r2[t+off]; }
        __syncthreads();
    }
    if (t == 0) {
        const float invN = 1.f / (32.f * 128.f * 128.f);
        float m = r0[0] * invN;
        g_mean[c] = m;
        g_sig[c]  = (r1[0] - m * r2[0]) * invN;
    }
}

// ---------------- kernel 3: fused local mean/MAD/blend ----------------
// grid (32 quads, 16 tiles, 32 batch), 256 threads, 4 CTAs/SM.
// smem (bytes):
//   sx @ 0     : [42][42] float4 = 28224  (TMA load target), pad -> 28288
//   hx @ 28288 : [42][37] uint2 (half2x2) = 12432, pad -> 12544 (ends 40832)
//   df @ 40832 : [37][37] uint2 (half2x2) = 10952 (ends 51784)
//   ob @ 28288 : [32][32] float4 = 16384 — aliases hx + head of df, both dead
//                after stage D's register compute (barrier-separated).
#define N_SX (42*42)
#define OFF_SX 0
#define OFF_HX 28288
#define OFF_DF 40832
#define OFF_OB 28288
#define SMEMB 51840

__global__ __launch_bounds__(256, 4)
void k_main(const __grid_constant__ CUtensorMap tmin,
            const __grid_constant__ CUtensorMap tmout,
            const float* __restrict__ x,
            const float* __restrict__ gamma,
            const float* __restrict__ beta,
            const float* __restrict__ lbin,
            float* __restrict__ out,
            int use_tma)
{
    extern __shared__ __align__(128) char smdyn[];
    float4* sx  = (float4*)(smdyn + OFF_SX);   // [42][42] fp32
    uint2*  hxh = (uint2*)(smdyn + OFF_HX);    // [42][37] half2x2 (reused as hd in C)
    uint2*  df  = (uint2*)(smdyn + OFF_DF);    // [37][37] half2x2
    float4* ob  = (float4*)(smdyn + OFF_OB);   // [32][32] fp32, aliases hx/df after D

    __shared__ __align__(8) uint64_t mbar;
    __shared__ float invW[37], invH[37];

    const int tx = threadIdx.x;
    const int quad = blockIdx.x;
    const int ox = (blockIdx.y & 3) * 32;
    const int oy = (blockIdx.y >> 2) * 32;
    const int b  = blockIdx.z;

    const uint32_t mb = s2u(&mbar);

    if (tx == 0) MBAR_INIT(mb, 1);
    __syncthreads();

    if (use_tma) {
        if (tx == 0) {
            MBAR_EXPECT_TX(mb, (uint32_t)(N_SX * 16));
            asm volatile(
                "cp.async.bulk.tensor.4d.shared::cta.global.tile.mbarrier::complete_tx::bytes "
                "[%0], [%1, {%2, %3, %4, %5}], [%6];"
                :: "r"(s2u(sx)), "l"(&tmin),
                   "r"(quad * 4), "r"(ox - 4), "r"(oy - 4), "r"(b),
                   "r"(mb) : "memory");
        }
    } else {
        const float4* xb = (const float4*)x;
        for (int p = tx; p < N_SX; p += 256) {
            int iy = p / 42, ix = p - iy * 42;
            int gr = oy - 4 + iy, gc = ox - 4 + ix;
            float4 v = f4zero();
            if ((unsigned)gr < 128u && (unsigned)gc < 128u)
                v = xb[((size_t)b * 16384 + gr * 128 + gc) * 32 + quad];
            sx[p] = v;
        }
    }

    // inverse window counts (overlaps the load)
    if (tx >= 160 && tx < 234) {
        int k = tx - 160;
        if (k < 37) invW[k] = 1.f / cntf(ox - 2 + k);
        else        invH[k - 37] = 1.f / cntf(oy - 2 + (k - 37));
    }

    if (use_tma) { MBAR_WAIT(mb, 0); }
    else __syncthreads();

    // Stage A: horizontal 6-box of x -> hx (fp16 packed). 252 threads:
    // (row y, chunk of 7 outputs). 12 contiguous fp32 reads/thread; conflict-free.
    if (tx < 252) {
        int y = tx / 6;
        int j0 = (tx % 6) * 7;
        const float4* row = sx + y * 42;
        float4 v[12];
        #pragma unroll
        for (int k = 0; k < 12; ++k)
            v[k] = (j0 + k <= 41) ? row[j0 + k] : f4zero();
        uint2* hrow = hxh + y * 37;
        float4 s = f4add(f4add(f4add(v[0], v[1]), f4add(v[2], v[3])), v[4]);
        #pragma unroll
        for (int k = 0; k < 7; ++k) {
            s = f4add(s, v[k + 5]);
            if (j0 + k <= 36) hrow[j0 + k] = f4_to_h2x2(s);
            s = f4sub(s, v[k]);
        }
    }
    __syncthreads();

    // Stage B: vertical 6-box -> local mean; df = x - lm (0 outside image), fp16.
    // 222 threads: (col j, 6 segments of 7/6 rows). Running sum in fp32;
    // enter/exit reads load identical fp16 bits -> exact cancellation.
    if (tx < 222) {
        int j = tx % 37, seg = tx / 37;
        int r0 = (seg == 0) ? 0 : (6 * seg + 1);
        int rn = (seg == 0) ? 7 : 6;
        float iw = invW[j];
        int gc = ox - 2 + j;
        bool cin = ((unsigned)gc < 128u);
        const uint2* hcol = hxh + j;
        float4 s = f4zero();
        #pragma unroll
        for (int k = 0; k < 5; ++k)
            s = f4add(s, h2x2_to_f4(hcol[(r0 + k) * 37]));
        #pragma unroll 7
        for (int it = 0; it < rn; ++it) {
            int r = r0 + it;
            s = f4add(s, h2x2_to_f4(hcol[(r + 5) * 37]));
            int gr = oy - 2 + r;
            float ic = iw * invH[r];
            float4 xv = sx[(r + 2) * 42 + (j + 2)];
            float4 dv = f4zero();
            if (cin && (unsigned)gr < 128u) {
                dv.x = xv.x - s.x * ic;
                dv.y = xv.y - s.y * ic;
                dv.z = xv.z - s.z * ic;
                dv.w = xv.w - s.w * ic;
            }
            df[r * 37 + j] = f4_to_h2x2(dv);
            s = f4sub(s, h2x2_to_f4(hcol[r * 37]));
        }
    }
    __syncthreads();

    // Stage C: horizontal 6-box of |df| -> hd (reuses hx region, fp16). 185 threads:
    // (row r = tx%37 lane-fast; chunk of 7 outputs). |.| via sign-mask on packed bits.
    if (tx < 185) {
        int r = tx % 37;
        int u0 = (tx / 37) * 7;
        const uint2* drow = df + r * 37;
        float4 v[12];
        #pragma unroll
        for (int k = 0; k < 12; ++k) {
            if (u0 + k <= 36) {
                uint2 p = drow[u0 + k];
                p.x &= 0x7FFF7FFFu;
                p.y &= 0x7FFF7FFFu;
                v[k] = h2x2_to_f4(p);
            } else {
                v[k] = f4zero();
            }
        }
        uint2* hrow = hxh + r * 37;
        float4 s = f4add(f4add(f4add(v[0], v[1]), f4add(v[2], v[3])), v[4]);
        #pragma unroll
        for (int k = 0; k < 7; ++k) {
            s = f4add(s, v[k + 5]);
            if (u0 + k <= 31) hrow[u0 + k] = f4_to_h2x2(s);
            s = f4sub(s, v[k]);
        }
    }
    __syncthreads();

    // Stage D: vertical 6-box of hd -> mad; blend + affine.
    // 256 threads: (col u, 8 segments of 4 rows). fp32 running sum over fp16 hd.
    float4 o[4];
    {
        int u = tx & 31, seg = tx >> 5;
        int v0 = seg * 4;
        float iw = invW[u + 2];

        float4 mn = ((const float4*)g_mean)[quad];
        float4 sg = ((const float4*)g_sig)[quad];
        float4 ga = ((const float4*)gamma)[quad];
        float4 be = ((const float4*)beta)[quad];
        float4 wt = ((const float4*)lbin)[quad];
        float4 Aq = make_float4(wt.x*ga.x, wt.y*ga.y, wt.z*ga.z, wt.w*ga.w);
        float4 Bq = make_float4(__fdividef((1.f-wt.x)*ga.x, sg.x+EPSF),
                                __fdividef((1.f-wt.y)*ga.y, sg.y+EPSF),
                                __fdividef((1.f-wt.z)*ga.z, sg.z+EPSF),
                                __fdividef((1.f-wt.w)*ga.w, sg.w+EPSF));
        float4 Dq = make_float4(be.x - Bq.x*mn.x, be.y - Bq.y*mn.y,
                                be.z - Bq.z*mn.z, be.w - Bq.w*mn.w);

        const uint2* hcol = hxh + u;
        float4 s = f4zero();
        #pragma unroll
        for (int k = 0; k < 5; ++k)
            s = f4add(s, h2x2_to_f4(hcol[(v0 + k) * 37]));
        #pragma unroll
        for (int it = 0; it < 4; ++it) {
            int v = v0 + it;
            s = f4add(s, h2x2_to_f4(hcol[(v + 5) * 37]));
            float ic = iw * invH[v + 2];
            float4 xv = sx[(v + 4) * 42 + (u + 4)];
            float4 nm = h2x2_to_f4(df[(v + 2) * 37 + (u + 2)]);
            o[it].x = Aq.x * __fdividef(nm.x, fmaf(s.x, ic, EPSF)) + fmaf(Bq.x, xv.x, Dq.x);
            o[it].y = Aq.y * __fdividef(nm.y, fmaf(s.y, ic, EPSF)) + fmaf(Bq.y, xv.y, Dq.y);
            o[it].z = Aq.z * __fdividef(nm.z, fmaf(s.z, ic, EPSF)) + fmaf(Bq.z, xv.z, Dq.z);
            o[it].w = Aq.w * __fdividef(nm.w, fmaf(s.w, ic, EPSF)) + fmaf(Bq.w, xv.w, Dq.w);
            s = f4sub(s, h2x2_to_f4(hcol[v * 37]));
        }
    }
    __syncthreads();   // all hx/df reads done; safe to overwrite with ob
    {
        int u = tx & 31, v0 = (tx >> 5) * 4;
        #pragma unroll
        for (int it = 0; it < 4; ++it)
            ob[(v0 + it) * 32 + u] = o[it];
    }
    __syncthreads();

    if (use_tma) {
        if (tx == 0) {
            asm volatile("fence.proxy.async.shared::cta;" ::: "memory");
            asm volatile(
                "cp.async.bulk.tensor.4d.global.shared::cta.tile.bulk_group "
                "[%0, {%1, %2, %3, %4}], [%5];"
                :: "l"(&tmout), "r"(quad * 4), "r"(ox), "r"(oy), "r"(b), "r"(s2u(ob))
                : "memory");
            asm volatile("cp.async.bulk.commit_group;" ::: "memory");
            asm volatile("cp.async.bulk.wait_group 0;" ::: "memory");
        }
    } else {
        float4* op = (float4*)out;
        for (int p = tx; p < 1024; p += 256) {
            int v = p >> 5, u = p & 31;
            op[((size_t)b * 16384 + (oy + v) * 128 + (ox + u)) * 32 + quad] = ob[p];
        }
    }
}

// ---------------- host ----------------
typedef CUresult (*EncodeTiledFn)(
    CUtensorMap*, CUtensorMapDataType, cuuint32_t, void*,
    const cuuint64_t*, const cuuint64_t*, const cuuint32_t*, const cuuint32_t*,
    CUtensorMapInterleave, CUtensorMapSwizzle, CUtensorMapL2promotion, CUtensorMapFloatOOBfill);

extern "C" void kernel_launch(void* const* d_in, const int* in_sizes, int n_in,
                              void* d_out, int out_size)
{
    (void)in_sizes; (void)n_in; (void)out_size;
    const float* x     = (const float*)d_in[0];
    const float* gamma = (const float*)d_in[1];
    const float* beta  = (const float*)d_in[2];
    const float* lbin  = (const float*)d_in[3];
    float* out = (float*)d_out;

    CUtensorMap tmin, tmout;
    int use_tma = 0;
    {
        EncodeTiledFn enc = nullptr;
        cudaDriverEntryPointQueryResult qr;
        if (cudaGetDriverEntryPoint("cuTensorMapEncodeTiled", (void**)&enc,
                                    cudaEnableDefault, &qr) == cudaSuccess && enc) {
            cuuint64_t dims[4]    = {128, 128, 128, 32};
            cuuint64_t strides[3] = {512, 65536, 8388608};   // bytes for dims 1..3
            cuuint32_t es[4]      = {1, 1, 1, 1};
            cuuint32_t box_in[4]  = {4, 42, 42, 1};
            cuuint32_t box_out[4] = {4, 32, 32, 1};
            CUresult r1 = enc(&tmin, CU_TENSOR_MAP_DATA_TYPE_FLOAT32, 4, (void*)x,
                              dims, strides, box_in, es,
                              CU_TENSOR_MAP_INTERLEAVE_NONE, CU_TENSOR_MAP_SWIZZLE_NONE,
                              CU_TENSOR_MAP_L2_PROMOTION_L2_128B, CU_TENSOR_MAP_FLOAT_OOB_FILL_NONE);
            CUresult r2 = enc(&tmout, CU_TENSOR_MAP_DATA_TYPE_FLOAT32, 4, (void*)d_out,
                              dims, strides, box_out, es,
                              CU_TENSOR_MAP_INTERLEAVE_NONE, CU_TENSOR_MAP_SWIZZLE_NONE,
                              CU_TENSOR_MAP_L2_PROMOTION_L2_128B, CU_TENSOR_MAP_FLOAT_OOB_FILL_NONE);
            use_tma = (r1 == CUDA_SUCCESS && r2 == CUDA_SUCCESS) ? 1 : 0;
        }
    }

    cudaFuncSetAttribute(k_main, cudaFuncAttributeMaxDynamicSharedMemorySize, SMEMB);

    const int n4 = (32 * 128 * 128 * 128) / 4;
    k_stats<<<SBLK, 256>>>((const float4*)x, n4);
    k_reduce<<<128, 128>>>();
    dim3 grid(32, 16, 32);
    k_main<<<grid, 256, SMEMB>>>(tmin, tmout, x, gamma, beta, lbin, out, use_tma);
}